// round 1
// baseline (speedup 1.0000x reference)
#include <cuda_runtime.h>
#include <cuda_bf16.h>
#include <math.h>

// Problem constants
#define BB 64
#define TT 1024
#define DD 128
#define HH 256

// Scratch: two ping-pong buffers of [B*T*H] floats (64 MB each).
// bufA: xw0 (layer-1 input proj), later u2 (layer-2 input proj)
// bufB: h1 (layer-1 hidden states)
__device__ float g_bufA[(size_t)BB * TT * HH];
__device__ float g_bufB[(size_t)BB * TT * HH];

// ---------------------------------------------------------------------------
// GEMM: C[M,N] = A[M,K] @ W[N,K]^T + b1[n] + b2[n]
// Tiles: BM=128, BN=64, BK=16; 256 threads; TM=8, TN=4 per thread.
// M % 128 == 0, N % 64 == 0, K % 16 == 0 (holds: M=65536, N=256, K=128/256)
// ---------------------------------------------------------------------------
__global__ __launch_bounds__(256)
void gemm_bias_kernel(const float* __restrict__ A,
                      const float* __restrict__ W,
                      const float* __restrict__ b1,
                      const float* __restrict__ b2,
                      float* __restrict__ C,
                      int M, int N, int K)
{
    __shared__ float As[16][128];
    __shared__ float Ws[16][64];

    const int m0 = blockIdx.y * 128;
    const int n0 = blockIdx.x * 64;
    const int tid = threadIdx.x;
    const int tr = tid >> 4;   // 0..15 -> rows tr*8 .. tr*8+7
    const int tc = tid & 15;   // 0..15 -> cols tc*4 .. tc*4+3

    float acc[8][4];
#pragma unroll
    for (int i = 0; i < 8; i++)
#pragma unroll
        for (int l = 0; l < 4; l++) acc[i][l] = 0.0f;

    for (int k0 = 0; k0 < K; k0 += 16) {
        // Load A tile (128x16) transposed into As[k][m]
#pragma unroll
        for (int it = 0; it < 2; it++) {
            int id  = tid + it * 256;       // 0..511
            int row = id >> 2;              // 0..127
            int c4  = (id & 3) << 2;        // 0,4,8,12
            float4 v = *(const float4*)&A[(size_t)(m0 + row) * K + k0 + c4];
            As[c4 + 0][row] = v.x;
            As[c4 + 1][row] = v.y;
            As[c4 + 2][row] = v.z;
            As[c4 + 3][row] = v.w;
        }
        // Load W tile (64x16) transposed into Ws[k][n]
        {
            int row = tid >> 2;             // 0..63
            int c4  = (tid & 3) << 2;
            float4 v = *(const float4*)&W[(size_t)(n0 + row) * K + k0 + c4];
            Ws[c4 + 0][row] = v.x;
            Ws[c4 + 1][row] = v.y;
            Ws[c4 + 2][row] = v.z;
            Ws[c4 + 3][row] = v.w;
        }
        __syncthreads();

#pragma unroll
        for (int k = 0; k < 16; k++) {
            float a[8], w[4];
#pragma unroll
            for (int i = 0; i < 8; i++) a[i] = As[k][tr * 8 + i];
#pragma unroll
            for (int l = 0; l < 4; l++) w[l] = Ws[k][tc * 4 + l];
#pragma unroll
            for (int i = 0; i < 8; i++)
#pragma unroll
                for (int l = 0; l < 4; l++)
                    acc[i][l] += a[i] * w[l];
        }
        __syncthreads();
    }

#pragma unroll
    for (int l = 0; l < 4; l++) {
        int n = n0 + tc * 4 + l;
        float bb = b1[n] + b2[n];
#pragma unroll
        for (int i = 0; i < 8; i++) {
            C[(size_t)(m0 + tr * 8 + i) * N + n] = acc[i][l] + bb;
        }
    }
}

// ---------------------------------------------------------------------------
// Recurrence: one CTA per batch element, 256 threads, thread j owns row j.
//   h_t[j] = tanh( xw[b,t,j] + sum_k W_hh[j,k] * h_{t-1}[k] )
// W_hh[j, 0:128]   -> 128 fp32 registers per thread
// W_hh[:, 128:256] -> SMEM, transposed (k-major) for conflict-free LDS
// TRANS=false: out[b,t,j] (layer 1) ; TRANS=true: out[b,j,t] (final layout)
// ---------------------------------------------------------------------------
template <bool TRANS>
__global__ __launch_bounds__(256, 1)
void rec_kernel(const float* __restrict__ xw,    // [B, T, H]
                const float* __restrict__ Whh,   // [H, H]
                float* __restrict__ out)
{
    extern __shared__ float sm[];
    float* Wsm   = sm;                    // [128][256]: Wsm[k*256 + j] = Whh[j][128+k]
    float* hbuf0 = sm + 128 * HH;         // 256
    float* hbuf1 = hbuf0 + HH;            // 256

    const int j = threadIdx.x;
    const int b = blockIdx.x;

    // Register half of this thread's weight row
    float wreg[128];
#pragma unroll
    for (int k = 0; k < 128; k += 4) {
        float4 v = *(const float4*)&Whh[(size_t)j * HH + k];
        wreg[k + 0] = v.x; wreg[k + 1] = v.y;
        wreg[k + 2] = v.z; wreg[k + 3] = v.w;
    }
    // SMEM half, stored transposed
#pragma unroll
    for (int k = 0; k < 128; k += 4) {
        float4 v = *(const float4*)&Whh[(size_t)j * HH + 128 + k];
        Wsm[(k + 0) * HH + j] = v.x;
        Wsm[(k + 1) * HH + j] = v.y;
        Wsm[(k + 2) * HH + j] = v.z;
        Wsm[(k + 3) * HH + j] = v.w;
    }
    hbuf0[j] = 0.0f;
    __syncthreads();

    float* hc = hbuf0;
    float* hn = hbuf1;

    const float* xp = xw + (size_t)b * TT * HH + j;
    float xin = xp[0];

    for (int t = 0; t < TT; ++t) {
        // Prefetch next step's input projection early
        float xnext = (t + 1 < TT) ? xp[(size_t)(t + 1) * HH] : 0.0f;

        float a0 = xin, a1 = 0.0f, a2 = 0.0f, a3 = 0.0f;

        const float4* h4 = (const float4*)hc;
        // k = 0..127 : weights from registers, h broadcast from SMEM
#pragma unroll
        for (int k = 0; k < 128; k += 4) {
            float4 hv = h4[k >> 2];
            a0 += wreg[k + 0] * hv.x;
            a1 += wreg[k + 1] * hv.y;
            a2 += wreg[k + 2] * hv.z;
            a3 += wreg[k + 3] * hv.w;
        }
        // k = 128..255 : weights from SMEM (k-major), h broadcast
        const float4* h4b = (const float4*)(hc + 128);
#pragma unroll
        for (int k = 0; k < 128; k += 4) {
            float4 hv = h4b[k >> 2];
            a0 += Wsm[(k + 0) * HH + j] * hv.x;
            a1 += Wsm[(k + 1) * HH + j] * hv.y;
            a2 += Wsm[(k + 2) * HH + j] * hv.z;
            a3 += Wsm[(k + 3) * HH + j] * hv.w;
        }

        float hval = tanhf((a0 + a1) + (a2 + a3));
        hn[j] = hval;
        if (TRANS) {
            out[((size_t)b * HH + j) * TT + t] = hval;
        } else {
            out[((size_t)b * TT + t) * HH + j] = hval;
        }
        xin = xnext;
        __syncthreads();
        float* tmp = hc; hc = hn; hn = tmp;
    }
}

// ---------------------------------------------------------------------------
// Launch
// ---------------------------------------------------------------------------
extern "C" void kernel_launch(void* const* d_in, const int* in_sizes, int n_in,
                              void* d_out, int out_size)
{
    const float* x     = (const float*)d_in[0];
    const float* W_ih0 = (const float*)d_in[1];
    const float* W_hh0 = (const float*)d_in[2];
    const float* b_ih0 = (const float*)d_in[3];
    const float* b_hh0 = (const float*)d_in[4];
    const float* W_ih1 = (const float*)d_in[5];
    const float* W_hh1 = (const float*)d_in[6];
    const float* b_ih1 = (const float*)d_in[7];
    const float* b_hh1 = (const float*)d_in[8];
    float* out = (float*)d_out;

    float *bufA, *bufB;
    cudaGetSymbolAddress((void**)&bufA, g_bufA);
    cudaGetSymbolAddress((void**)&bufB, g_bufB);

    const int rec_smem = (128 * HH + 2 * HH) * (int)sizeof(float);  // 133120 B
    cudaFuncSetAttribute(rec_kernel<false>,
                         cudaFuncAttributeMaxDynamicSharedMemorySize, rec_smem);
    cudaFuncSetAttribute(rec_kernel<true>,
                         cudaFuncAttributeMaxDynamicSharedMemorySize, rec_smem);

    const int M = BB * TT;  // 65536

    // Layer 1 input projection: bufA = x @ W_ih0^T + (b_ih0 + b_hh0)
    gemm_bias_kernel<<<dim3(HH / 64, M / 128), 256>>>(
        x, W_ih0, b_ih0, b_hh0, bufA, M, HH, DD);

    // Layer 1 recurrence -> bufB = h1 [B,T,H]
    rec_kernel<false><<<BB, 256, rec_smem>>>(bufA, W_hh0, bufB);

    // Layer 2 input projection: bufA = h1 @ W_ih1^T + (b_ih1 + b_hh1)
    gemm_bias_kernel<<<dim3(HH / 64, M / 128), 256>>>(
        bufB, W_ih1, b_ih1, b_hh1, bufA, M, HH, HH);

    // Layer 2 recurrence -> out [B,H,T]
    rec_kernel<true><<<BB, 256, rec_smem>>>(bufA, W_hh1, out);
}

// round 3
// speedup vs baseline: 1.1178x; 1.1178x over previous
#include <cuda_runtime.h>
#include <cuda_bf16.h>
#include <math.h>
#include <stdint.h>

// Problem constants
#define BB 64
#define TT 1024
#define DD 128
#define HH 256

// Scratch ping-pong buffers [B*T*H] fp32 (64 MB each)
__device__ float g_bufA[(size_t)BB * TT * HH];
__device__ float g_bufB[(size_t)BB * TT * HH];

// ---------------------------------------------------------------------------
// helpers
// ---------------------------------------------------------------------------
__device__ __forceinline__ uint32_t smem_u32(const void* p) {
    uint32_t a;
    asm("{ .reg .u64 t; cvta.to.shared.u64 t, %1; cvt.u32.u64 %0, t; }"
        : "=r"(a) : "l"(p));
    return a;
}

__device__ __forceinline__ void mbar_init(uint32_t addr, uint32_t count) {
    asm volatile("mbarrier.init.shared.b64 [%0], %1;" :: "r"(addr), "r"(count) : "memory");
}

// acquire at cluster scope: makes peer's st.shared::cluster (released by its
// mbarrier.arrive) visible to this CTA.
__device__ __forceinline__ void mbar_wait_parity_acq_cluster(uint32_t addr, uint32_t parity) {
    asm volatile(
        "{\n\t"
        ".reg .pred P;\n\t"
        "WAIT_LOOP_%=:\n\t"
        "mbarrier.try_wait.parity.acquire.cluster.shared::cta.b64 P, [%0], %1, 0x989680;\n\t"
        "@!P bra WAIT_LOOP_%=;\n\t"
        "}"
        :: "r"(addr), "r"(parity) : "memory");
}

// ---------------------------------------------------------------------------
// GEMM: C[M,N] = A[M,K] @ W[N,K]^T + b1[n] + b2[n]
// BM=128, BN=128, BK=16, 256 threads, TM=8, TN=8
// ---------------------------------------------------------------------------
__global__ __launch_bounds__(256)
void gemm_bias_kernel(const float* __restrict__ A,
                      const float* __restrict__ W,
                      const float* __restrict__ b1,
                      const float* __restrict__ b2,
                      float* __restrict__ C,
                      int M, int N, int K)
{
    __shared__ float As[16][128];
    __shared__ float Ws[16][128];

    const int m0 = blockIdx.y * 128;
    const int n0 = blockIdx.x * 128;
    const int tid = threadIdx.x;
    const int tr = tid >> 4;   // 0..15 -> rows tr*8..+7
    const int tc = tid & 15;   // 0..15 -> cols tc*8..+7

    float acc[8][8];
#pragma unroll
    for (int i = 0; i < 8; i++)
#pragma unroll
        for (int l = 0; l < 8; l++) acc[i][l] = 0.0f;

    for (int k0 = 0; k0 < K; k0 += 16) {
        // A tile 128x16 -> As[k][m] (transposed)
#pragma unroll
        for (int it = 0; it < 2; it++) {
            int id  = tid + it * 256;       // 0..511
            int row = id >> 2;              // 0..127
            int c4  = (id & 3) << 2;
            float4 v = *(const float4*)&A[(size_t)(m0 + row) * K + k0 + c4];
            As[c4 + 0][row] = v.x;
            As[c4 + 1][row] = v.y;
            As[c4 + 2][row] = v.z;
            As[c4 + 3][row] = v.w;
        }
        // W tile 128x16 -> Ws[k][n] (transposed)
#pragma unroll
        for (int it = 0; it < 2; it++) {
            int id  = tid + it * 256;
            int row = id >> 2;
            int c4  = (id & 3) << 2;
            float4 v = *(const float4*)&W[(size_t)(n0 + row) * K + k0 + c4];
            Ws[c4 + 0][row] = v.x;
            Ws[c4 + 1][row] = v.y;
            Ws[c4 + 2][row] = v.z;
            Ws[c4 + 3][row] = v.w;
        }
        __syncthreads();

#pragma unroll
        for (int k = 0; k < 16; k++) {
            float a[8], w[8];
#pragma unroll
            for (int i = 0; i < 8; i++) a[i] = As[k][tr * 8 + i];
#pragma unroll
            for (int l = 0; l < 8; l++) w[l] = Ws[k][tc * 8 + l];
#pragma unroll
            for (int i = 0; i < 8; i++)
#pragma unroll
                for (int l = 0; l < 8; l++)
                    acc[i][l] += a[i] * w[l];
        }
        __syncthreads();
    }

    float bb[8];
#pragma unroll
    for (int l = 0; l < 8; l++) {
        int n = n0 + tc * 8 + l;
        bb[l] = b1[n] + b2[n];
    }
#pragma unroll
    for (int i = 0; i < 8; i++) {
        float* crow = &C[(size_t)(m0 + tr * 8 + i) * N + n0 + tc * 8];
        float4 v0, v1;
        v0.x = acc[i][0] + bb[0]; v0.y = acc[i][1] + bb[1];
        v0.z = acc[i][2] + bb[2]; v0.w = acc[i][3] + bb[3];
        v1.x = acc[i][4] + bb[4]; v1.y = acc[i][5] + bb[5];
        v1.z = acc[i][6] + bb[6]; v1.w = acc[i][7] + bb[7];
        *(float4*)crow       = v0;
        *(float4*)(crow + 4) = v1;
    }
}

// ---------------------------------------------------------------------------
// Recurrence, 2-CTA cluster per batch element.
//   CTA rank r owns outputs j in [r*128, r*128+128).
//   Thread t: jl = t&127, kh = t>>7. Thread computes partial dot over
//   k in [kh*128, kh*128+128) with 64 packed f32x2 weight registers.
//   Pair (jl, kh=0/1) reduced via smem; kh=0 threads apply tanh, write h
//   into local + peer SMEM (double-buffered), arrive on both mbarriers.
// ---------------------------------------------------------------------------
template <bool TRANS>
__global__ __launch_bounds__(256, 1) __cluster_dims__(2, 1, 1)
void rec_cluster_kernel(const float* __restrict__ xw,    // [B, T, H]
                        const float* __restrict__ Whh,   // [H, H]
                        float* __restrict__ out)
{
    __shared__ __align__(16) float hb[2][HH];
    __shared__ float red[128];
    __shared__ uint64_t mbar;

    const int t0 = threadIdx.x;
    const int jl = t0 & 127;
    const int kh = t0 >> 7;
    uint32_t rank;
    asm("mov.u32 %0, %%cluster_ctarank;" : "=r"(rank));
    const int b = blockIdx.x >> 1;
    const int j = (int)rank * 128 + jl;

    // 128 fp32 weights = 64 packed f32x2 pairs, all in registers.
    uint64_t w[64];
    const uint64_t* wrow = (const uint64_t*)(Whh + (size_t)j * HH + (kh << 7));
#pragma unroll
    for (int i = 0; i < 64; i++) w[i] = wrow[i];

    hb[0][t0] = 0.0f;
    hb[1][t0] = 0.0f;
    const uint32_t mb = smem_u32(&mbar);
    if (t0 == 0) mbar_init(mb, 256);   // 128 local + 128 remote arrivals/step
    __syncthreads();
    // both CTAs' mbar init + h zero must precede any remote traffic
    asm volatile("barrier.cluster.arrive.aligned;" ::: "memory");
    asm volatile("barrier.cluster.wait.aligned;"   ::: "memory");

    const uint32_t peer = rank ^ 1u;
    uint32_t r_h0, r_h1, r_mb;
    {
        uint32_t l_h0 = smem_u32(&hb[0][j]);
        uint32_t l_h1 = smem_u32(&hb[1][j]);
        asm("mapa.shared::cluster.u32 %0, %1, %2;" : "=r"(r_h0) : "r"(l_h0), "r"(peer));
        asm("mapa.shared::cluster.u32 %0, %1, %2;" : "=r"(r_h1) : "r"(l_h1), "r"(peer));
        asm("mapa.shared::cluster.u32 %0, %1, %2;" : "=r"(r_mb) : "r"(mb),   "r"(peer));
    }

    const float* xp = xw + (size_t)b * TT * HH + j;
    float xin = xp[0];

    int p = 0;
    for (int t = 0; t < TT; ++t) {
        if (t) mbar_wait_parity_acq_cluster(mb, (uint32_t)((t - 1) & 1));

        float xnext = (t + 1 < TT) ? xp[(size_t)(t + 1) * HH] : 0.0f;

        const uint64_t* h2 = (const uint64_t*)(hb[p] + (kh << 7));
        uint64_t a0 = 0ull, a1 = 0ull, a2 = 0ull, a3 = 0ull;
#pragma unroll
        for (int i = 0; i < 64; i += 4) {
            asm("fma.rn.f32x2 %0, %1, %2, %0;" : "+l"(a0) : "l"(w[i + 0]), "l"(h2[i + 0]));
            asm("fma.rn.f32x2 %0, %1, %2, %0;" : "+l"(a1) : "l"(w[i + 1]), "l"(h2[i + 1]));
            asm("fma.rn.f32x2 %0, %1, %2, %0;" : "+l"(a2) : "l"(w[i + 2]), "l"(h2[i + 2]));
            asm("fma.rn.f32x2 %0, %1, %2, %0;" : "+l"(a3) : "l"(w[i + 3]), "l"(h2[i + 3]));
        }
        asm("add.rn.f32x2 %0, %0, %1;" : "+l"(a0) : "l"(a1));
        asm("add.rn.f32x2 %0, %0, %1;" : "+l"(a2) : "l"(a3));
        asm("add.rn.f32x2 %0, %0, %1;" : "+l"(a0) : "l"(a2));
        uint32_t lo, hi;
        asm("mov.b64 {%0, %1}, %2;" : "=r"(lo), "=r"(hi) : "l"(a0));
        float part = __uint_as_float(lo) + __uint_as_float(hi);

        if (kh) red[jl] = part;
        __syncthreads();   // consumers finished reading hb[p] after this

        if (!kh) {
            float v = xin + part + red[jl];
            float hval;
            asm("tanh.approx.f32 %0, %1;" : "=f"(hval) : "f"(v));

            if (p == 0) {
                hb[1][j] = hval;
                asm volatile("st.shared::cluster.f32 [%0], %1;" :: "r"(r_h1), "f"(hval) : "memory");
            } else {
                hb[0][j] = hval;
                asm volatile("st.shared::cluster.f32 [%0], %1;" :: "r"(r_h0), "f"(hval) : "memory");
            }

            if (TRANS) out[((size_t)b * HH + j) * TT + t] = hval;
            else       out[((size_t)b * TT + t) * HH + j] = hval;

            // local arrive (release) then remote arrive (release, cluster)
            asm volatile("mbarrier.arrive.release.cluster.shared::cta.b64 _, [%0];"
                         :: "r"(mb) : "memory");
            asm volatile("mbarrier.arrive.shared::cluster.b64 _, [%0];"
                         :: "r"(r_mb) : "memory");
        }
        xin = xnext;
        p ^= 1;
    }

    // no CTA may exit while peer-targeted stores/arrives are in flight
    asm volatile("barrier.cluster.arrive.aligned;" ::: "memory");
    asm volatile("barrier.cluster.wait.aligned;"   ::: "memory");
}

// ---------------------------------------------------------------------------
// Launch
// ---------------------------------------------------------------------------
extern "C" void kernel_launch(void* const* d_in, const int* in_sizes, int n_in,
                              void* d_out, int out_size)
{
    const float* x     = (const float*)d_in[0];
    const float* W_ih0 = (const float*)d_in[1];
    const float* W_hh0 = (const float*)d_in[2];
    const float* b_ih0 = (const float*)d_in[3];
    const float* b_hh0 = (const float*)d_in[4];
    const float* W_ih1 = (const float*)d_in[5];
    const float* W_hh1 = (const float*)d_in[6];
    const float* b_ih1 = (const float*)d_in[7];
    const float* b_hh1 = (const float*)d_in[8];
    float* out = (float*)d_out;

    float *bufA, *bufB;
    cudaGetSymbolAddress((void**)&bufA, g_bufA);
    cudaGetSymbolAddress((void**)&bufB, g_bufB);

    const int M = BB * TT;  // 65536

    // Layer 1 input projection: bufA = x @ W_ih0^T + (b_ih0 + b_hh0)
    gemm_bias_kernel<<<dim3(HH / 128, M / 128), 256>>>(
        x, W_ih0, b_ih0, b_hh0, bufA, M, HH, DD);

    // Layer 1 recurrence -> bufB = h1 [B,T,H]   (64 clusters of 2 CTAs)
    rec_cluster_kernel<false><<<BB * 2, 256>>>(bufA, W_hh0, bufB);

    // Layer 2 input projection: bufA = h1 @ W_ih1^T + (b_ih1 + b_hh1)
    gemm_bias_kernel<<<dim3(HH / 128, M / 128), 256>>>(
        bufB, W_ih1, b_ih1, b_hh1, bufA, M, HH, HH);

    // Layer 2 recurrence -> out [B,H,T]
    rec_cluster_kernel<true><<<BB * 2, 256>>>(bufA, W_hh1, out);
}

// round 4
// speedup vs baseline: 1.4913x; 1.3341x over previous
#include <cuda_runtime.h>
#include <cuda_bf16.h>
#include <math.h>
#include <stdint.h>

// Problem constants
#define BB 64
#define TT 1024
#define DD 128
#define HH 256

// Scratch ping-pong buffers [B*T*H] fp32 (64 MB each)
__device__ float g_bufA[(size_t)BB * TT * HH];
__device__ float g_bufB[(size_t)BB * TT * HH];

// ---------------------------------------------------------------------------
// helpers
// ---------------------------------------------------------------------------
__device__ __forceinline__ uint32_t smem_u32(const void* p) {
    uint32_t a;
    asm("{ .reg .u64 t; cvta.to.shared.u64 t, %1; cvt.u32.u64 %0, t; }"
        : "=r"(a) : "l"(p));
    return a;
}

__device__ __forceinline__ void mbar_init(uint32_t addr, uint32_t count) {
    asm volatile("mbarrier.init.shared.b64 [%0], %1;" :: "r"(addr), "r"(count) : "memory");
}

__device__ __forceinline__ void mbar_wait_parity_acq_cluster(uint32_t addr, uint32_t parity) {
    asm volatile(
        "{\n\t"
        ".reg .pred P;\n\t"
        "WAIT_LOOP_%=:\n\t"
        "mbarrier.try_wait.parity.acquire.cluster.shared::cta.b64 P, [%0], %1, 0x989680;\n\t"
        "@!P bra WAIT_LOOP_%=;\n\t"
        "}"
        :: "r"(addr), "r"(parity) : "memory");
}

// ---------------------------------------------------------------------------
// GEMM: C[M,N] = A[M,K] @ W[N,K]^T + b1[n] + b2[n]
// BM=128, BN=128, BK=16, 256 threads, TM=8, TN=8, packed f32x2 accumulators.
// ---------------------------------------------------------------------------
__global__ __launch_bounds__(256)
void gemm_bias_kernel(const float* __restrict__ A,
                      const float* __restrict__ W,
                      const float* __restrict__ b1,
                      const float* __restrict__ b2,
                      float* __restrict__ C,
                      int M, int N, int K)
{
    __shared__ float As[16][128];
    __shared__ float Ws[16][128];

    const int m0 = blockIdx.y * 128;
    const int n0 = blockIdx.x * 128;
    const int tid = threadIdx.x;
    const int tr = tid >> 4;   // 0..15 -> rows tr*8..+7
    const int tc = tid & 15;   // 0..15 -> cols tc*8..+7

    // acc2[i][l] holds output cols (tc*8 + 2l, tc*8 + 2l + 1) for row tr*8+i
    uint64_t acc2[8][4];
#pragma unroll
    for (int i = 0; i < 8; i++)
#pragma unroll
        for (int l = 0; l < 4; l++) acc2[i][l] = 0ull;

    for (int k0 = 0; k0 < K; k0 += 16) {
        // A tile 128x16 -> As[k][m] (transposed)
#pragma unroll
        for (int it = 0; it < 2; it++) {
            int id  = tid + it * 256;       // 0..511
            int row = id >> 2;              // 0..127
            int c4  = (id & 3) << 2;
            float4 v = *(const float4*)&A[(size_t)(m0 + row) * K + k0 + c4];
            As[c4 + 0][row] = v.x;
            As[c4 + 1][row] = v.y;
            As[c4 + 2][row] = v.z;
            As[c4 + 3][row] = v.w;
        }
        // W tile 128x16 -> Ws[k][n] (transposed)
#pragma unroll
        for (int it = 0; it < 2; it++) {
            int id  = tid + it * 256;
            int row = id >> 2;
            int c4  = (id & 3) << 2;
            float4 v = *(const float4*)&W[(size_t)(n0 + row) * K + k0 + c4];
            Ws[c4 + 0][row] = v.x;
            Ws[c4 + 1][row] = v.y;
            Ws[c4 + 2][row] = v.z;
            Ws[c4 + 3][row] = v.w;
        }
        __syncthreads();

#pragma unroll
        for (int k = 0; k < 16; k++) {
            float a[8];
#pragma unroll
            for (int i = 0; i < 8; i++) a[i] = As[k][tr * 8 + i];
            // w pairs: 4 uint64 covering cols tc*8 .. tc*8+7
            uint64_t w2[4];
            const uint64_t* wp = (const uint64_t*)&Ws[k][tc * 8];
#pragma unroll
            for (int l = 0; l < 4; l++) w2[l] = wp[l];
#pragma unroll
            for (int i = 0; i < 8; i++) {
                uint64_t a2;
                asm("mov.b64 %0, {%1, %1};" : "=l"(a2) : "f"(a[i]));
#pragma unroll
                for (int l = 0; l < 4; l++)
                    asm("fma.rn.f32x2 %0, %1, %2, %0;"
                        : "+l"(acc2[i][l]) : "l"(a2), "l"(w2[l]));
            }
        }
        __syncthreads();
    }

    float bb[8];
#pragma unroll
    for (int l = 0; l < 8; l++) {
        int n = n0 + tc * 8 + l;
        bb[l] = b1[n] + b2[n];
    }
#pragma unroll
    for (int i = 0; i < 8; i++) {
        float r[8];
#pragma unroll
        for (int l = 0; l < 4; l++) {
            uint32_t lo, hi;
            asm("mov.b64 {%0, %1}, %2;" : "=r"(lo), "=r"(hi) : "l"(acc2[i][l]));
            r[2 * l]     = __uint_as_float(lo) + bb[2 * l];
            r[2 * l + 1] = __uint_as_float(hi) + bb[2 * l + 1];
        }
        float* crow = &C[(size_t)(m0 + tr * 8 + i) * N + n0 + tc * 8];
        *(float4*)crow       = make_float4(r[0], r[1], r[2], r[3]);
        *(float4*)(crow + 4) = make_float4(r[4], r[5], r[6], r[7]);
    }
}

// ---------------------------------------------------------------------------
// Recurrence, 2-CTA cluster per batch element.
//   CTA rank r owns outputs j in [r*128, r*128+128).
//   Thread t: jl = t&127, kh = t>>7; partial dot over k in [kh*128, +128)
//   with 64 packed f32x2 weight registers (all W_hh in RF across the cluster).
//   Sync per step:
//     - threads with kh == rank read locally-produced h, ordered by the
//       end-of-step __syncthreads (bar2) -> NO mbar wait.
//     - threads with kh != rank wait the mbar (count=128, remote arrivals
//       only, arrive.release.cluster / try_wait.acquire.cluster).
// ---------------------------------------------------------------------------
template <bool TRANS>
__global__ __launch_bounds__(256, 1) __cluster_dims__(2, 1, 1)
void rec_cluster_kernel(const float* __restrict__ xw,    // [B, T, H]
                        const float* __restrict__ Whh,   // [H, H]
                        float* __restrict__ out)
{
    __shared__ __align__(16) float hb[2][HH];
    __shared__ float red[128];
    __shared__ uint64_t mbar;

    const int t0 = threadIdx.x;
    const int jl = t0 & 127;
    const int kh = t0 >> 7;
    uint32_t rank;
    asm("mov.u32 %0, %%cluster_ctarank;" : "=r"(rank));
    const int b = blockIdx.x >> 1;
    const int j = (int)rank * 128 + jl;
    const bool need_peer = (kh != (int)rank);

    // 128 fp32 weights = 64 packed f32x2 pairs, all in registers.
    uint64_t w[64];
    const uint64_t* wrow = (const uint64_t*)(Whh + (size_t)j * HH + (kh << 7));
#pragma unroll
    for (int i = 0; i < 64; i++) w[i] = wrow[i];

    hb[0][t0] = 0.0f;
    hb[1][t0] = 0.0f;
    const uint32_t mb = smem_u32(&mbar);
    if (t0 == 0) mbar_init(mb, 128);   // 128 REMOTE arrivals per step
    __syncthreads();
    // both CTAs' mbar init + h zero must precede any remote traffic
    asm volatile("barrier.cluster.arrive.aligned;" ::: "memory");
    asm volatile("barrier.cluster.wait.aligned;"   ::: "memory");

    const uint32_t peer = rank ^ 1u;
    uint32_t r_h0, r_h1, r_mb;
    {
        uint32_t l_h0 = smem_u32(&hb[0][j]);
        uint32_t l_h1 = smem_u32(&hb[1][j]);
        asm("mapa.shared::cluster.u32 %0, %1, %2;" : "=r"(r_h0) : "r"(l_h0), "r"(peer));
        asm("mapa.shared::cluster.u32 %0, %1, %2;" : "=r"(r_h1) : "r"(l_h1), "r"(peer));
        asm("mapa.shared::cluster.u32 %0, %1, %2;" : "=r"(r_mb) : "r"(mb),   "r"(peer));
    }

    const float* xp = xw + (size_t)b * TT * HH + j;
    float xin = xp[0];

    int p = 0;
    for (int t = 0; t < TT; ++t) {
        // Peer-half threads wait for the peer's h writes of step t-1.
        // Local-half threads were ordered by bar2 of the previous iteration.
        if (t && need_peer) mbar_wait_parity_acq_cluster(mb, (uint32_t)((t - 1) & 1));

        float xnext = (t + 1 < TT) ? xp[(size_t)(t + 1) * HH] : 0.0f;

        const uint64_t* h2 = (const uint64_t*)(hb[p] + (kh << 7));
        uint64_t a0 = 0ull, a1 = 0ull, a2 = 0ull, a3 = 0ull;
#pragma unroll
        for (int i = 0; i < 64; i += 4) {
            asm("fma.rn.f32x2 %0, %1, %2, %0;" : "+l"(a0) : "l"(w[i + 0]), "l"(h2[i + 0]));
            asm("fma.rn.f32x2 %0, %1, %2, %0;" : "+l"(a1) : "l"(w[i + 1]), "l"(h2[i + 1]));
            asm("fma.rn.f32x2 %0, %1, %2, %0;" : "+l"(a2) : "l"(w[i + 2]), "l"(h2[i + 2]));
            asm("fma.rn.f32x2 %0, %1, %2, %0;" : "+l"(a3) : "l"(w[i + 3]), "l"(h2[i + 3]));
        }
        asm("add.rn.f32x2 %0, %0, %1;" : "+l"(a0) : "l"(a1));
        asm("add.rn.f32x2 %0, %0, %1;" : "+l"(a2) : "l"(a3));
        asm("add.rn.f32x2 %0, %0, %1;" : "+l"(a0) : "l"(a2));
        uint32_t lo, hi;
        asm("mov.b64 {%0, %1}, %2;" : "=r"(lo), "=r"(hi) : "l"(a0));
        float part = __uint_as_float(lo) + __uint_as_float(hi);

        if (kh) red[jl] = part;
        __syncthreads();   // bar1: reduce join; also: all reads of hb[p] done

        float hval = 0.0f;
        if (!kh) {
            float v = xin + part + red[jl];
            asm("tanh.approx.f32 %0, %1;" : "=f"(hval) : "f"(v));
            hb[p ^ 1][j] = hval;          // local publish (ordered by bar2)
        }
        __syncthreads();   // bar2: local h of step t visible to local half

        if (!kh) {
            // remote publish + arrive (release at cluster scope)
            asm volatile("st.shared::cluster.f32 [%0], %1;"
                         :: "r"(p ? r_h0 : r_h1), "f"(hval) : "memory");
            asm volatile("mbarrier.arrive.release.cluster.shared::cluster.b64 _, [%0];"
                         :: "r"(r_mb) : "memory");
            // out-store AFTER the arrive: off the peer's critical path
            if (TRANS) out[((size_t)b * HH + j) * TT + t] = hval;
            else       out[((size_t)b * TT + t) * HH + j] = hval;
        }
        xin = xnext;
        p ^= 1;
    }

    // no CTA may exit while peer-targeted stores/arrives are in flight
    asm volatile("barrier.cluster.arrive.aligned;" ::: "memory");
    asm volatile("barrier.cluster.wait.aligned;"   ::: "memory");
}

// ---------------------------------------------------------------------------
// Launch
// ---------------------------------------------------------------------------
extern "C" void kernel_launch(void* const* d_in, const int* in_sizes, int n_in,
                              void* d_out, int out_size)
{
    const float* x     = (const float*)d_in[0];
    const float* W_ih0 = (const float*)d_in[1];
    const float* W_hh0 = (const float*)d_in[2];
    const float* b_ih0 = (const float*)d_in[3];
    const float* b_hh0 = (const float*)d_in[4];
    const float* W_ih1 = (const float*)d_in[5];
    const float* W_hh1 = (const float*)d_in[6];
    const float* b_ih1 = (const float*)d_in[7];
    const float* b_hh1 = (const float*)d_in[8];
    float* out = (float*)d_out;

    float *bufA, *bufB;
    cudaGetSymbolAddress((void**)&bufA, g_bufA);
    cudaGetSymbolAddress((void**)&bufB, g_bufB);

    const int M = BB * TT;  // 65536

    // Layer 1 input projection: bufA = x @ W_ih0^T + (b_ih0 + b_hh0)
    gemm_bias_kernel<<<dim3(HH / 128, M / 128), 256>>>(
        x, W_ih0, b_ih0, b_hh0, bufA, M, HH, DD);

    // Layer 1 recurrence -> bufB = h1 [B,T,H]   (64 clusters of 2 CTAs)
    rec_cluster_kernel<false><<<BB * 2, 256>>>(bufA, W_hh0, bufB);

    // Layer 2 input projection: bufA = h1 @ W_ih1^T + (b_ih1 + b_hh1)
    gemm_bias_kernel<<<dim3(HH / 128, M / 128), 256>>>(
        bufB, W_ih1, b_ih1, b_hh1, bufA, M, HH, HH);

    // Layer 2 recurrence -> out [B,H,T]
    rec_cluster_kernel<true><<<BB * 2, 256>>>(bufA, W_hh1, out);
}